// round 5
// baseline (speedup 1.0000x reference)
#include <cuda_runtime.h>

#define NPOINTS 100000
#define BATCH   4096
#define KSEL    10
#define TILE    8192
#define NWARPS  32
#define RPW     4
#define THREADS 1024
#define CHUNK   64
#define NSPLIT  4
#define SPLITPTS 25000
#define SPLITPAD 25088         // 392 * 64
#define FULLMASK 0xffffffffu

typedef unsigned long long ull;

// partial top-K scratch: [split][ray][k]
__device__ float g_pd[NSPLIT][BATCH][KSEL];
__device__ int   g_pi[NSPLIT][BATCH][KSEL];

static __device__ __forceinline__ ull fma2(ull a, ull b, ull c) {
    ull d;
    asm("fma.rn.f32x2 %0, %1, %2, %3;" : "=l"(d) : "l"(a), "l"(b), "l"(c));
    return d;
}
static __device__ __forceinline__ ull pack2(float lo, float hi) {
    ull d;
    asm("mov.b64 %0, {%1, %2};" : "=l"(d) : "f"(lo), "f"(hi));
    return d;
}
static __device__ __forceinline__ void unpack2(ull v, float& lo, float& hi) {
    asm("mov.b64 {%0, %1}, %2;" : "=f"(lo), "=f"(hi) : "l"(v));
}
static __device__ __forceinline__ float sigmoidf_(float x) {
    return 1.0f / (1.0f + expf(-x));
}

// ---------------------------------------------------------------------------
// Kernel 1: scan one quarter of the points for 128 rays per block
// ---------------------------------------------------------------------------
__global__ __launch_bounds__(THREADS, 1)
void gsplat_scan_kernel(const float* __restrict__ rays_o,
                        const float* __restrict__ rays_d,
                        const float* __restrict__ xyz)
{
    extern __shared__ float sm[];
    float* Xs = sm;
    float* Ys = sm + TILE;
    float* Zs = sm + 2 * TILE;
    float* Ws = sm + 3 * TILE;
    float* Hd = sm + 4 * TILE;                                  // [warp][ray][k]
    int*   Hi = (int*)(sm + 4 * TILE + NWARPS * RPW * KSEL);

    const int tid   = threadIdx.x;
    const int lane  = tid & 31;
    const int wid   = tid >> 5;
    const int split = blockIdx.x & (NSPLIT - 1);
    const int ray0  = ((blockIdx.x >> 2) * NWARPS + wid) * RPW;

    const float POSINF = __int_as_float(0x7f800000);

    float* hd = Hd + (wid * RPW) * KSEL;
    int*   hi = Hi + (wid * RPW) * KSEL;

    ull A[RPW], B[RPW], C[RPW];
    float thr[RPW];
    #pragma unroll
    for (int r = 0; r < RPW; r++) {
        int ray = ray0 + r;
        float ox = rays_o[3*ray+0], oy = rays_o[3*ray+1], oz = rays_o[3*ray+2];
        float dx = rays_d[3*ray+0], dy = rays_d[3*ray+1], dz = rays_d[3*ray+2];
        float cx = fmaf(dx, 3.0f, ox);
        float cy = fmaf(dy, 3.0f, oy);
        float cz = fmaf(dz, 3.0f, oz);
        A[r] = pack2(-2.0f*cx, -2.0f*cx);
        B[r] = pack2(-2.0f*cy, -2.0f*cy);
        C[r] = pack2(-2.0f*cz, -2.0f*cz);
        thr[r] = POSINF;
    }
    #pragma unroll
    for (int r = 0; r < RPW; r++)
        #pragma unroll
        for (int j = 0; j < KSEL; j++) { hd[r*KSEL+j] = POSINF; hi[r*KSEL+j] = 0; }

    const int base = split * SPLITPTS;
    const int hend = base + SPLITPTS;

    for (int t0 = base; t0 < base + SPLITPAD; t0 += TILE) {
        int tsz = min(TILE, base + SPLITPAD - t0);   // 8192 or 512 (mult of 64)
        __syncthreads();
        for (int s = tid; s < tsz; s += THREADS) {
            int g = t0 + s;
            float px = 0.f, py = 0.f, pz = 0.f, pw = POSINF;
            if (g < hend) {
                px = xyz[3*g+0]; py = xyz[3*g+1]; pz = xyz[3*g+2];
                pw = fmaf(px, px, fmaf(py, py, pz*pz));
            }
            Xs[s] = px; Ys[s] = py; Zs[s] = pz; Ws[s] = pw;
        }
        __syncthreads();

        const ull* X64 = (const ull*)Xs;
        const ull* Y64 = (const ull*)Ys;
        const ull* Z64 = (const ull*)Zs;
        const ull* W64 = (const ull*)Ws;

        const int nch = tsz / CHUNK;
        for (int ch = 0; ch < nch; ch++) {
            const int hb = ch * (CHUNK / 2);
            ull x0 = X64[hb + lane];
            ull y0 = Y64[hb + lane];
            ull z0 = Z64[hb + lane];
            ull w0 = W64[hb + lane];

            float klo[RPW], khi[RPW], lm[RPW];
            #pragma unroll
            for (int r = 0; r < RPW; r++) {
                ull k = fma2(x0, A[r], fma2(y0, B[r], fma2(z0, C[r], w0)));
                unpack2(k, klo[r], khi[r]);
                lm[r] = fminf(klo[r], khi[r]);
            }

            bool trig = (lm[0] < thr[0]) | (lm[1] < thr[1]) |
                        (lm[2] < thr[2]) | (lm[3] < thr[3]);
            if (__any_sync(FULLMASK, trig)) {
                const int pbase = t0 + ch * CHUNK;
                #pragma unroll
                for (int r = 0; r < RPW; r++) {
                    unsigned mr = __ballot_sync(FULLMASK, lm[r] < thr[r]);
                    while (mr) {
                        int src = __ffs(mr) - 1;
                        mr &= mr - 1;
                        float vlo = __shfl_sync(FULLMASK, klo[r], src);
                        float vhi = __shfl_sync(FULLMASK, khi[r], src);
                        int ibase = pbase + 2 * src;
                        #pragma unroll
                        for (int q = 0; q < 2; q++) {
                            float kv = q ? vhi : vlo;
                            int   ki = ibase + q;
                            if (kv < thr[r]) {   // warp-uniform; smem bubble insert
                                float v = kv; int vi = ki;
                                #pragma unroll
                                for (int jj = 0; jj < KSEL; jj++) {
                                    float cur = hd[r*KSEL+jj];
                                    int   ci  = hi[r*KSEL+jj];
                                    if (v < cur) {
                                        hd[r*KSEL+jj] = v;  hi[r*KSEL+jj] = vi;
                                        v = cur; vi = ci;
                                    }
                                }
                                thr[r] = hd[r*KSEL+KSEL-1];
                            }
                        }
                    }
                }
            }
        }
    }

    if (lane < KSEL) {
        #pragma unroll
        for (int r = 0; r < RPW; r++) {
            int ray = ray0 + r;
            g_pd[split][ray][lane] = hd[r*KSEL+lane];
            g_pi[split][ray][lane] = hi[r*KSEL+lane];
        }
    }
}

// ---------------------------------------------------------------------------
// Kernel 2: merge the four partial top-10 lists per ray, run the epilogue
// ---------------------------------------------------------------------------
__global__ __launch_bounds__(32)
void gsplat_merge_kernel(const float* __restrict__ rays_o,
                         const float* __restrict__ rays_d,
                         const float* __restrict__ fdc,
                         const float* __restrict__ opacity,
                         float* __restrict__ out)
{
    int ray = blockIdx.x * blockDim.x + threadIdx.x;
    if (ray >= BATCH) return;

    const float POSINF = __int_as_float(0x7f800000);

    float ox = rays_o[3*ray+0], oy = rays_o[3*ray+1], oz = rays_o[3*ray+2];
    float dx = rays_d[3*ray+0], dy = rays_d[3*ray+1], dz = rays_d[3*ray+2];
    float cx = fmaf(dx, 3.0f, ox);
    float cy = fmaf(dy, 3.0f, oy);
    float cz = fmaf(dz, 3.0f, oz);
    float cn2 = cx*cx + cy*cy + cz*cz;

    float bd[KSEL]; int bi[KSEL];
    #pragma unroll
    for (int j = 0; j < KSEL; j++) { bd[j] = POSINF; bi[j] = 0; }

    #pragma unroll
    for (int h = 0; h < NSPLIT; h++) {
        #pragma unroll
        for (int k = 0; k < KSEL; k++) {
            float v = g_pd[h][ray][k];
            int  vi = g_pi[h][ray][k];
            #pragma unroll
            for (int j = 0; j < KSEL; j++) {
                if (v < bd[j]) {
                    float tv = bd[j]; bd[j] = v;  v  = tv;
                    int   ti = bi[j]; bi[j] = vi; vi = ti;
                }
            }
        }
    }

    float ws = 0.f, s0 = 0.f, s1 = 0.f, s2 = 0.f;
    #pragma unroll
    for (int k = 0; k < KSEL; k++) {
        float sq = bd[k] + cn2;
        float dist = sqrtf(fmaxf(sq, 0.0f));
        int id = bi[k];
        float op = opacity[id];
        float w = expf(-0.1f * dist) * sigmoidf_(op);
        ws += w;
        float f0 = fdc[3*id+0], f1 = fdc[3*id+1], f2 = fdc[3*id+2];
        s0 = fmaf(w, sigmoidf_(f0), s0);
        s1 = fmaf(w, sigmoidf_(f1), s1);
        s2 = fmaf(w, sigmoidf_(f2), s2);
    }
    float inv = 1.0f / (ws + 1e-8f);
    out[3*ray+0] = s0 * inv;
    out[3*ray+1] = s1 * inv;
    out[3*ray+2] = s2 * inv;
}

extern "C" void kernel_launch(void* const* d_in, const int* in_sizes, int n_in,
                              void* d_out, int out_size)
{
    const float* rays_o  = (const float*)d_in[0];
    const float* rays_d  = (const float*)d_in[1];
    const float* xyz     = (const float*)d_in[2];
    const float* fdc     = (const float*)d_in[3];
    const float* opacity = (const float*)d_in[4];
    float* out = (float*)d_out;

    const int smem = 4 * TILE * sizeof(float)
                   + 2 * NWARPS * RPW * KSEL * sizeof(float);   // 128KB + 10KB
    static bool attr_set = false;
    if (!attr_set) {
        cudaFuncSetAttribute(gsplat_scan_kernel,
                             cudaFuncAttributeMaxDynamicSharedMemorySize, smem);
        attr_set = true;
    }

    // 128 blocks: (32 ray-groups of 128 rays) x (4 point splits)
    gsplat_scan_kernel<<<dim3(NSPLIT * BATCH / (NWARPS * RPW)), dim3(THREADS), smem>>>(
        rays_o, rays_d, xyz);
    gsplat_merge_kernel<<<dim3(BATCH / 32), dim3(32)>>>(
        rays_o, rays_d, fdc, opacity, out);
}